// round 12
// baseline (speedup 1.0000x reference)
#include <cuda_runtime.h>
#include <cstdint>

#define BNUM 4
#define HS 64
#define WS 64
#define HU 512
#define WU 512
#define CORI 90
#define CMNT 180
#define COFF 8
#define KCAND 1024
#define NCELL (HS*WS)       // 4096
#define NPIX (HU*WU)        // 262144

// output layout (concatenated flattened returns):
// minut [4,1024,4] | keep [4,1024] | enh_vis [4,512,512] | mask_up*255 | ori_field
#define MINUT_OFF 0
#define KEEP_OFF  16384
#define ENH_OFF   20480
#define MASK_OFF  1069056
#define ORI_OFF   2117632

// -------- device scratch --------
__device__ float g_mask[BNUM*NCELL];
__device__ float g_er[BNUM*NCELL];
__device__ float g_tA[BNUM*NPIX];
__device__ float g_tB[BNUM*NPIX];
__device__ float g_maskup[BNUM*NPIX];
__device__ unsigned g_emin[BNUM];
__device__ unsigned g_emax[BNUM];
__device__ unsigned g_eminP[BNUM*32];   // spread atomic slots
__device__ unsigned g_emaxP[BNUM*32];

__device__ __forceinline__ unsigned f2ord(float f){
    unsigned u=__float_as_uint(f);
    return (u & 0x80000000u) ? ~u : (u | 0x80000000u);
}
__device__ __forceinline__ float ord2f(unsigned u){
    u = (u & 0x80000000u) ? (u & 0x7fffffffu) : ~u;
    return __uint_as_float(u);
}

// -------- small 5x5 opening on [B,64,64] (+ minmax slot init) --------
__global__ void small_erode(const float* __restrict__ seg){
    int i=blockIdx.x*blockDim.x+threadIdx.x;
    if(i<BNUM){ g_emin[i]=0xFFFFFFFFu; g_emax[i]=0u; }
    if(i<BNUM*32){ g_eminP[i]=0xFFFFFFFFu; g_emaxP[i]=0u; }
    if(i>=BNUM*NCELL) return;
    int b=i/NCELL, cell=i%NCELL, r=cell/WS, c=cell%WS;
    const float* s=seg+(size_t)b*NCELL;
    int y0=r-2<0?0:r-2, y1=r+2>HS-1?HS-1:r+2;
    int x0=c-2<0?0:c-2, x1=c+2>WS-1?WS-1:c+2;
    float m=1e30f;
    for(int y=y0;y<=y1;y++)
        for(int x=x0;x<=x1;x++)
            m=fminf(m, rintf(s[y*WS+x]));
    g_er[i]=m;
}
__global__ void small_dilate(){
    int i=blockIdx.x*blockDim.x+threadIdx.x;
    if(i>=BNUM*NCELL) return;
    int b=i/NCELL, cell=i%NCELL, r=cell/WS, c=cell%WS;
    const float* s=g_er+(size_t)b*NCELL;
    int y0=r-2<0?0:r-2, y1=r+2>HS-1?HS-1:r+2;
    int x0=c-2<0?0:c-2, x1=c+2>WS-1?WS-1:c+2;
    float m=-1e30f;
    for(int y=y0;y<=y1;y++)
        for(int x=x0;x<=x1;x++)
            m=fmaxf(m, s[y*WS+x]);
    g_mask[i]=m;
}

// -------- vertical brute pools (HEAVY ANCHORS, unchanged from 60.2us base) --------
__device__ __forceinline__ float poolV(const float* s, int y, int x, bool isMin, bool doRound){
    int a0=y-19; if(a0<0)a0=0;
    int a1=y+20; if(a1>HU-1)a1=HU-1;
    float m = isMin?1e30f:-1e30f;
    for(int yy=a0;yy<=a1;yy++){
        float v=s[yy*WU+x];
        if(doRound)v=rintf(v);
        m = isMin?fminf(m,v):fmaxf(m,v);
    }
    return m;
}
__global__ void up1_vmin(const float* __restrict__ segup){
    int i=blockIdx.x*blockDim.x+threadIdx.x; if(i>=BNUM*NPIX)return;
    int b=i/NPIX, p=i%NPIX;
    g_tA[i]=poolV(segup+(size_t)b*NPIX, p/WU, p%WU, true, true);
}
__global__ void up3_vmax(){
    int i=blockIdx.x*blockDim.x+threadIdx.x; if(i>=BNUM*NPIX)return;
    int b=i/NPIX, p=i%NPIX;
    g_tA[i]=poolV(g_tB+(size_t)b*NPIX, p/WU, p%WU, false, false);
}

// -------- horizontal float4 quad pool (light, sandwiched) --------
// 4 outputs/thread. quads q=0..10 cover k=0..43 (k = x-(x0-20)); output j needs
// k in [j+1, j+40]: core=op(qm[1..9]); edges from quad0 (e1..e3) / quad10 (f0..f2).
template<bool MN, bool FUSED>
__global__ void __launch_bounds__(256) up_h4(const float* __restrict__ in, float* __restrict__ out,
                                             const float* __restrict__ enh, float* __restrict__ outg){
    int i=blockIdx.x*256+threadIdx.x;
    if(i>=BNUM*NPIX/4) return;
    int b=i/(NPIX/4); int rem=i%(NPIX/4);
    int row=rem/(WU/4); int x0=(rem%(WU/4))*4;
    const float* rp = in + (size_t)b*NPIX + (size_t)row*WU;
    const float NEU=MN?1e30f:-1e30f;
    #define OPX(a,c) (MN?fminf(a,c):fmaxf(a,c))
    float qm[11];
    float e1,e2,e3,f0,f1,f2;
    #pragma unroll
    for(int q=0;q<11;q++){
        int bs=x0-20+4*q;
        float a0,a1,a2,a3;
        if(bs>=0 && bs+3<WU){
            float4 v=*reinterpret_cast<const float4*>(rp+bs);
            a0=v.x; a1=v.y; a2=v.z; a3=v.w;
        } else {
            a0=(bs  >=0 && bs  <WU)? rp[bs  ] : NEU;
            a1=(bs+1>=0 && bs+1<WU)? rp[bs+1] : NEU;
            a2=(bs+2>=0 && bs+2<WU)? rp[bs+2] : NEU;
            a3=(bs+3>=0 && bs+3<WU)? rp[bs+3] : NEU;
        }
        if(q==0){ e1=a1; e2=a2; e3=a3; }
        if(q==10){ f0=a0; f1=a1; f2=a2; }
        qm[q]=OPX(OPX(a0,a1),OPX(a2,a3));
    }
    float core=qm[1];
    #pragma unroll
    for(int k=2;k<=9;k++) core=OPX(core,qm[k]);
    float4 o;
    o.x=OPX(OPX(core,OPX(e1,e2)),OPX(e3,f0));
    o.y=OPX(OPX(core,OPX(e2,e3)),OPX(f0,f1));
    o.z=OPX(OPX(core,e3),OPX(f0,OPX(f1,f2)));
    o.w=OPX(core,qm[10]);
    size_t off=(size_t)b*NPIX + (size_t)row*WU + x0;
    *reinterpret_cast<float4*>(out + off) = o;
    if(FUSED){
        float4 ev4=*reinterpret_cast<const float4*>(enh + off);
        float mn=fminf(fminf(ev4.x*o.x,ev4.y*o.y),fminf(ev4.z*o.z,ev4.w*o.w));
        float mx=fmaxf(fmaxf(ev4.x*o.x,ev4.y*o.y),fmaxf(ev4.z*o.z,ev4.w*o.w));
        #pragma unroll
        for(int s=16;s;s>>=1){
            mn=fminf(mn,__shfl_xor_sync(0xFFFFFFFFu,mn,s));
            mx=fmaxf(mx,__shfl_xor_sync(0xFFFFFFFFu,mx,s));
        }
        if((threadIdx.x&31)==0){
            int slot=b*32+((int)blockIdx.x&31);
            atomicMin(&g_eminP[slot], f2ord(mn));
            atomicMax(&g_emaxP[slot], f2ord(mx));
        }
    }
    #undef OPX
}

// -------- detect (top-k + NMS), one block per batch; + slot reduce at top --------
__global__ void __launch_bounds__(1024) detect_nms(
    const float* __restrict__ mscore, const float* __restrict__ mori,
    const float* __restrict__ mxo,    const float* __restrict__ myo,
    float* __restrict__ out)
{
    int b=blockIdx.x, tid=threadIdx.x;
    if(tid<32){
        unsigned vmn=g_eminP[b*32+tid];
        unsigned vmx=g_emaxP[b*32+tid];
        #pragma unroll
        for(int o=16;o;o>>=1){
            vmn=min(vmn,__shfl_xor_sync(0xFFFFFFFFu,vmn,o));
            vmx=max(vmx,__shfl_xor_sync(0xFFFFFFFFu,vmx,o));
        }
        if(tid==0){ g_emin[b]=vmn; g_emax[b]=vmx; }
    }
    __shared__ unsigned long long keys[4096];   // 32KB
    __shared__ int s_nv;
    float* sx=(float*)(keys+1024);
    float* sy=(float*)(keys+1536);
    float* sa=(float*)(keys+2048);
    unsigned char* skeep=(unsigned char*)(keys+2560);

    const float* sc=mscore+(size_t)b*NCELL;
    const float* mk=g_mask +(size_t)b*NCELL;

    bool anyv=false;
    for(int t=tid;t<NCELL;t+=1024){
        float v=sc[t]*mk[t];
        bool val = v>0.5f;
        anyv |= val;
        float mv = val ? v : -1.0f;
        keys[t] = ((unsigned long long)(~f2ord(mv))<<32) | (unsigned)t;
    }
    if(__syncthreads_count(anyv)==0){
        float* om=out + MINUT_OFF + (size_t)b*KCAND*4 + (size_t)tid*4;
        om[0]=0.0f; om[1]=0.0f; om[2]=0.0f; om[3]=0.0f;
        out[KEEP_OFF + (size_t)b*KCAND + tid]=0.0f;
        return;
    }
    for(int k=2;k<=4096;k<<=1){
        for(int j=k>>1;j>0;j>>=1){
            for(int i=tid;i<4096;i+=1024){
                int ixj=i^j;
                if(ixj>i){
                    unsigned long long a=keys[i], c=keys[ixj];
                    bool up=((i&k)==0);
                    if((a>c)==up){ keys[i]=c; keys[ixj]=a; }
                }
            }
            __syncthreads();
        }
    }
    unsigned long long key=keys[tid];
    int idx=(int)(key & 0xFFFFFFFFull);
    float score=sc[idx]*mk[idx];
    bool valid = score>0.5f;
    float xc=0.0f, yc=0.0f, ang=0.0f;
    if(!valid) score=0.0f;
    if(valid){
        int r=idx>>6, c=idx&63;
        const float* o=mori+(size_t)b*CMNT*NCELL+idx;
        int ai=0; float bv=o[0];
        for(int ch=1;ch<CMNT;ch++){ float v=o[(size_t)ch*NCELL]; if(v>bv){bv=v;ai=ch;} }
        const float* xo=mxo+(size_t)b*COFF*NCELL+idx;
        int xi=0; float bx=xo[0];
        for(int ch=1;ch<COFF;ch++){ float v=xo[(size_t)ch*NCELL]; if(v>bx){bx=v;xi=ch;} }
        const float* yo=myo+(size_t)b*COFF*NCELL+idx;
        int yi=0; float by=yo[0];
        for(int ch=1;ch<COFF;ch++){ float v=yo[(size_t)ch*NCELL]; if(v>by){by=v;yi=ch;} }
        ang=((float)ai*2.0f-89.0f)*0.017453292519943295f;
        xc=(float)c*8.0f+(float)xi;
        yc=(float)r*8.0f+(float)yi;
    }
    if(tid==0) s_nv=0;
    __syncthreads();
    sx[tid]=xc; sy[tid]=yc; sa[tid]=ang; skeep[tid]=valid?1:0;
    atomicMax(&s_nv, valid?(tid+1):0);
    __syncthreads();
    int nv=s_nv;
    for(int i=0;i<nv;i++){
        if(skeep[i] && tid>i && skeep[tid]){
            float dx=sx[tid]-sx[i], dy=sy[tid]-sy[i];
            float d=sqrtf(dx*dx+dy*dy);
            float da=fabsf(sa[tid]-sa[i]);
            da=fminf(da, 6.2831853071795864f-da);
            if(d<16.0f && da<0.52359877559829887f) skeep[tid]=0;
        }
        __syncthreads();
    }
    float kf = skeep[tid]?1.0f:0.0f;
    float* om=out + MINUT_OFF + (size_t)b*KCAND*4 + (size_t)tid*4;
    om[0]=kf*xc; om[1]=kf*yc; om[2]=kf*ang; om[3]=kf*score;
    out[KEEP_OFF + (size_t)b*KCAND + tid]=kf;
}

// -------- finalize: enh_vis, mask*255, ori_field (mask-predicated argmax) --------
__global__ void finalize(const float* __restrict__ enh, const float* __restrict__ oriup,
                         float* __restrict__ out){
    int i=blockIdx.x*blockDim.x+threadIdx.x;
    if(i>=BNUM*NPIX) return;
    int b=i/NPIX, p=i%NPIX;
    float m=g_maskup[i];
    out[MASK_OFF+i]=m*255.0f;
    float emin=ord2f(g_emin[b]);
    float emax=ord2f(g_emax[b]);
    float e=enh[i]*m;
    out[ENH_OFF+i]=(e-emin)/(emax-emin+1e-8f)*255.0f;
    float of=0.0f;
    if(m!=0.0f){
        const float* o=oriup+(size_t)b*CORI*NPIX+p;
        int ai=0; float bv=o[0];
        for(int ch=1;ch<CORI;ch++){ float v=o[(size_t)ch*NPIX]; if(v>bv){bv=v;ai=ch;} }
        of=((float)ai*2.0f-90.0f)*0.017453292519943295f*m;
    }
    out[ORI_OFF+i]=of;
}

extern "C" void kernel_launch(void* const* d_in, const int* in_sizes, int n_in,
                              void* d_out, int out_size){
    const float* seg    =(const float*)d_in[0];
    const float* segup  =(const float*)d_in[1];
    const float* oriup  =(const float*)d_in[2];
    const float* enh    =(const float*)d_in[3];
    const float* mscore =(const float*)d_in[4];
    const float* mori   =(const float*)d_in[5];
    const float* mxo    =(const float*)d_in[6];
    const float* myo    =(const float*)d_in[7];
    float* out=(float*)d_out;

    int nSmall=(BNUM*NCELL+255)/256;
    int nBig  =(BNUM*NPIX +255)/256;
    int nVec  =(BNUM*NPIX/4+255)/256;   // 1024 blocks

    small_erode<<<nSmall,256>>>(seg);    // includes minmax slot init
    small_dilate<<<nSmall,256>>>();

    up1_vmin<<<nBig,256>>>(segup);                               // HEAVY anchor
    up_h4<true ,false><<<nVec,256>>>(g_tA, g_tB, nullptr, nullptr); // light hmin
    up3_vmax<<<nBig,256>>>();                                    // HEAVY anchor
    up_h4<false,true ><<<nVec,256>>>(g_tA, g_maskup, enh, out);  // light hmax + fused minmax
    // note: up3 reads g_tB, writes g_tA; up_h4<false> reads g_tA -> correct chain

    detect_nms<<<BNUM,1024>>>(mscore, mori, mxo, myo, out);      // + slot reduce
    finalize<<<nBig,256>>>(enh, oriup, out);
}

// round 13
// speedup vs baseline: 2.2015x; 2.2015x over previous
#include <cuda_runtime.h>
#include <cstdint>

#define BNUM 4
#define HS 64
#define WS 64
#define HU 512
#define WU 512
#define CORI 90
#define CMNT 180
#define COFF 8
#define KCAND 1024
#define NCELL (HS*WS)       // 4096
#define NPIX (HU*WU)        // 262144

// output layout (concatenated flattened returns):
// minut [4,1024,4] | keep [4,1024] | enh_vis [4,512,512] | mask_up*255 | ori_field
#define MINUT_OFF 0
#define KEEP_OFF  16384
#define ENH_OFF   20480
#define MASK_OFF  1069056
#define ORI_OFF   2117632

// -------- device scratch --------
__device__ float g_mask[BNUM*NCELL];
__device__ float g_er[BNUM*NCELL];
__device__ float g_tA[BNUM*NPIX];
__device__ float g_tB[BNUM*NPIX];
__device__ float g_maskup[BNUM*NPIX];
__device__ unsigned g_emin[BNUM];
__device__ unsigned g_emax[BNUM];

__device__ __forceinline__ unsigned f2ord(float f){
    unsigned u=__float_as_uint(f);
    return (u & 0x80000000u) ? ~u : (u | 0x80000000u);
}
__device__ __forceinline__ float ord2f(unsigned u){
    u = (u & 0x80000000u) ? (u & 0x7fffffffu) : ~u;
    return __uint_as_float(u);
}

// -------- small 5x5 opening on [B,64,64] (+ minmax init) --------
__global__ void small_erode(const float* __restrict__ seg){
    int i=blockIdx.x*blockDim.x+threadIdx.x;
    if(i<BNUM){ g_emin[i]=0xFFFFFFFFu; g_emax[i]=0u; }
    if(i>=BNUM*NCELL) return;
    int b=i/NCELL, cell=i%NCELL, r=cell/WS, c=cell%WS;
    const float* s=seg+(size_t)b*NCELL;
    int y0=r-2<0?0:r-2, y1=r+2>HS-1?HS-1:r+2;
    int x0=c-2<0?0:c-2, x1=c+2>WS-1?WS-1:c+2;
    float m=1e30f;
    for(int y=y0;y<=y1;y++)
        for(int x=x0;x<=x1;x++)
            m=fminf(m, rintf(s[y*WS+x]));
    g_er[i]=m;
}
__global__ void small_dilate(){
    int i=blockIdx.x*blockDim.x+threadIdx.x;
    if(i>=BNUM*NCELL) return;
    int b=i/NCELL, cell=i%NCELL, r=cell/WS, c=cell%WS;
    const float* s=g_er+(size_t)b*NCELL;
    int y0=r-2<0?0:r-2, y1=r+2>HS-1?HS-1:r+2;
    int x0=c-2<0?0:c-2, x1=c+2>WS-1?WS-1:c+2;
    float m=-1e30f;
    for(int y=y0;y<=y1;y++)
        for(int x=x0;x<=x1;x++)
            m=fmaxf(m, s[y*WS+x]);
    g_mask[i]=m;
}

// -------- vertical brute pools (HEAVY ANCHORS, byte-identical to R8) --------
__device__ __forceinline__ float poolV(const float* s, int y, int x, bool isMin, bool doRound){
    int a0=y-19; if(a0<0)a0=0;
    int a1=y+20; if(a1>HU-1)a1=HU-1;
    float m = isMin?1e30f:-1e30f;
    for(int yy=a0;yy<=a1;yy++){
        float v=s[yy*WU+x];
        if(doRound)v=rintf(v);
        m = isMin?fminf(m,v):fmaxf(m,v);
    }
    return m;
}
__device__ __forceinline__ float poolH(const float* s, int y, int x, bool isMin){
    int a0=x-19; if(a0<0)a0=0;
    int a1=x+20; if(a1>WU-1)a1=WU-1;
    const float* row=s+(size_t)y*WU;
    float m = isMin?1e30f:-1e30f;
    for(int xx=a0;xx<=a1;xx++){
        float v=row[xx];
        m = isMin?fminf(m,v):fmaxf(m,v);
    }
    return m;
}
__global__ void up1_vmin(const float* __restrict__ segup){
    int i=blockIdx.x*blockDim.x+threadIdx.x; if(i>=BNUM*NPIX)return;
    int b=i/NPIX, p=i%NPIX;
    g_tA[i]=poolV(segup+(size_t)b*NPIX, p/WU, p%WU, true, true);
}
__global__ void up3_vmax(){
    int i=blockIdx.x*blockDim.x+threadIdx.x; if(i>=BNUM*NPIX)return;
    int b=i/NPIX, p=i%NPIX;
    g_tA[i]=poolV(g_tB+(size_t)b*NPIX, p/WU, p%WU, false, false);
}
__global__ void up4_hmax(){
    int i=blockIdx.x*blockDim.x+threadIdx.x; if(i>=BNUM*NPIX)return;
    int b=i/NPIX, p=i%NPIX;
    g_maskup[i]=poolH(g_tA+(size_t)b*NPIX, p/WU, p%WU, false);
}

// -------- hmin as float4 quad pool (light, sandwiched; 2.44us measured in this slot) --------
// 4 outputs/thread. quads q=0..10 cover k=0..43 (k = x-(x0-20)); output j needs
// k in [j+1, j+40]: core=op(qm[1..9]); edges from quad0 (e1..e3) / quad10 (f0..f2).
__global__ void __launch_bounds__(256) up2_h4min(){
    int i=blockIdx.x*256+threadIdx.x;
    if(i>=BNUM*NPIX/4) return;
    int b=i/(NPIX/4); int rem=i%(NPIX/4);
    int row=rem/(WU/4); int x0=(rem%(WU/4))*4;
    const float* rp = g_tA + (size_t)b*NPIX + (size_t)row*WU;
    const float NEU=1e30f;
    float qm[11];
    float e1,e2,e3,f0,f1,f2;
    #pragma unroll
    for(int q=0;q<11;q++){
        int bs=x0-20+4*q;
        float a0,a1,a2,a3;
        if(bs>=0 && bs+3<WU){
            float4 v=*reinterpret_cast<const float4*>(rp+bs);
            a0=v.x; a1=v.y; a2=v.z; a3=v.w;
        } else {
            a0=(bs  >=0 && bs  <WU)? rp[bs  ] : NEU;
            a1=(bs+1>=0 && bs+1<WU)? rp[bs+1] : NEU;
            a2=(bs+2>=0 && bs+2<WU)? rp[bs+2] : NEU;
            a3=(bs+3>=0 && bs+3<WU)? rp[bs+3] : NEU;
        }
        if(q==0){ e1=a1; e2=a2; e3=a3; }
        if(q==10){ f0=a0; f1=a1; f2=a2; }
        qm[q]=fminf(fminf(a0,a1),fminf(a2,a3));
    }
    float core=qm[1];
    #pragma unroll
    for(int k=2;k<=9;k++) core=fminf(core,qm[k]);
    float4 o;
    o.x=fminf(fminf(core,fminf(e1,e2)),fminf(e3,f0));
    o.y=fminf(fminf(core,fminf(e2,e3)),fminf(f0,f1));
    o.z=fminf(fminf(core,e3),fminf(f0,fminf(f1,f2)));
    o.w=fminf(core,qm[10]);
    *reinterpret_cast<float4*>(g_tB + (size_t)b*NPIX + (size_t)row*WU + x0) = o;
}

// -------- enhanced min/max per batch (R8 version) --------
__global__ void enh_minmax(const float* __restrict__ enh){
    int b=blockIdx.y;
    const float* e=enh+(size_t)b*NPIX;
    const float* m=g_maskup+(size_t)b*NPIX;
    float mn=1e30f, mx=-1e30f;
    for(int p=blockIdx.x*blockDim.x+threadIdx.x; p<NPIX; p+=gridDim.x*blockDim.x){
        float v=e[p]*m[p];
        mn=fminf(mn,v); mx=fmaxf(mx,v);
    }
    for(int o=16;o;o>>=1){
        mn=fminf(mn,__shfl_down_sync(0xFFFFFFFFu,mn,o));
        mx=fmaxf(mx,__shfl_down_sync(0xFFFFFFFFu,mx,o));
    }
    __shared__ float smn[8], smx[8];
    int lane=threadIdx.x&31, w=threadIdx.x>>5;
    if(lane==0){ smn[w]=mn; smx[w]=mx; }
    __syncthreads();
    if(threadIdx.x==0){
        int nw=blockDim.x>>5;
        for(int i=1;i<nw;i++){ mn=fminf(mn,smn[i]); mx=fmaxf(mx,smx[i]); }
        atomicMin(&g_emin[b], f2ord(mn));
        atomicMax(&g_emax[b], f2ord(mx));
    }
}

// -------- detect (top-k + NMS), one block per batch (R8 version) --------
__global__ void __launch_bounds__(1024) detect_nms(
    const float* __restrict__ mscore, const float* __restrict__ mori,
    const float* __restrict__ mxo,    const float* __restrict__ myo,
    float* __restrict__ out)
{
    int b=blockIdx.x, tid=threadIdx.x;
    __shared__ unsigned long long keys[4096];   // 32KB
    __shared__ int s_nv;
    float* sx=(float*)(keys+1024);
    float* sy=(float*)(keys+1536);
    float* sa=(float*)(keys+2048);
    unsigned char* skeep=(unsigned char*)(keys+2560);

    const float* sc=mscore+(size_t)b*NCELL;
    const float* mk=g_mask +(size_t)b*NCELL;

    bool anyv=false;
    for(int t=tid;t<NCELL;t+=1024){
        float v=sc[t]*mk[t];
        bool val = v>0.5f;
        anyv |= val;
        float mv = val ? v : -1.0f;
        keys[t] = ((unsigned long long)(~f2ord(mv))<<32) | (unsigned)t;
    }
    if(__syncthreads_count(anyv)==0){
        float* om=out + MINUT_OFF + (size_t)b*KCAND*4 + (size_t)tid*4;
        om[0]=0.0f; om[1]=0.0f; om[2]=0.0f; om[3]=0.0f;
        out[KEEP_OFF + (size_t)b*KCAND + tid]=0.0f;
        return;
    }

    for(int k=2;k<=4096;k<<=1){
        for(int j=k>>1;j>0;j>>=1){
            for(int i=tid;i<4096;i+=1024){
                int ixj=i^j;
                if(ixj>i){
                    unsigned long long a=keys[i], c=keys[ixj];
                    bool up=((i&k)==0);
                    if((a>c)==up){ keys[i]=c; keys[ixj]=a; }
                }
            }
            __syncthreads();
        }
    }

    unsigned long long key=keys[tid];
    int idx=(int)(key & 0xFFFFFFFFull);
    float score=sc[idx]*mk[idx];
    bool valid = score>0.5f;
    float xc=0.0f, yc=0.0f, ang=0.0f;
    if(!valid) score=0.0f;
    if(valid){
        int r=idx>>6, c=idx&63;
        const float* o=mori+(size_t)b*CMNT*NCELL+idx;
        int ai=0; float bv=o[0];
        for(int ch=1;ch<CMNT;ch++){ float v=o[(size_t)ch*NCELL]; if(v>bv){bv=v;ai=ch;} }
        const float* xo=mxo+(size_t)b*COFF*NCELL+idx;
        int xi=0; float bx=xo[0];
        for(int ch=1;ch<COFF;ch++){ float v=xo[(size_t)ch*NCELL]; if(v>bx){bx=v;xi=ch;} }
        const float* yo=myo+(size_t)b*COFF*NCELL+idx;
        int yi=0; float by=yo[0];
        for(int ch=1;ch<COFF;ch++){ float v=yo[(size_t)ch*NCELL]; if(v>by){by=v;yi=ch;} }
        ang=((float)ai*2.0f-89.0f)*0.017453292519943295f;
        xc=(float)c*8.0f+(float)xi;
        yc=(float)r*8.0f+(float)yi;
    }
    if(tid==0) s_nv=0;
    __syncthreads();
    sx[tid]=xc; sy[tid]=yc; sa[tid]=ang; skeep[tid]=valid?1:0;
    atomicMax(&s_nv, valid?(tid+1):0);
    __syncthreads();
    int nv=s_nv;
    for(int i=0;i<nv;i++){
        if(skeep[i] && tid>i && skeep[tid]){
            float dx=sx[tid]-sx[i], dy=sy[tid]-sy[i];
            float d=sqrtf(dx*dx+dy*dy);
            float da=fabsf(sa[tid]-sa[i]);
            da=fminf(da, 6.2831853071795864f-da);
            if(d<16.0f && da<0.52359877559829887f) skeep[tid]=0;
        }
        __syncthreads();
    }
    float kf = skeep[tid]?1.0f:0.0f;
    float* om=out + MINUT_OFF + (size_t)b*KCAND*4 + (size_t)tid*4;
    om[0]=kf*xc; om[1]=kf*yc; om[2]=kf*ang; om[3]=kf*score;
    out[KEEP_OFF + (size_t)b*KCAND + tid]=kf;
}

// -------- finalize: enh_vis, mask*255, ori_field (mask-predicated argmax) --------
__global__ void finalize(const float* __restrict__ enh, const float* __restrict__ oriup,
                         float* __restrict__ out){
    int i=blockIdx.x*blockDim.x+threadIdx.x;
    if(i>=BNUM*NPIX) return;
    int b=i/NPIX, p=i%NPIX;
    float m=g_maskup[i];
    out[MASK_OFF+i]=m*255.0f;
    float emin=ord2f(g_emin[b]);
    float emax=ord2f(g_emax[b]);
    float e=enh[i]*m;
    out[ENH_OFF+i]=(e-emin)/(emax-emin+1e-8f)*255.0f;
    float of=0.0f;
    if(m!=0.0f){
        const float* o=oriup+(size_t)b*CORI*NPIX+p;
        int ai=0; float bv=o[0];
        for(int ch=1;ch<CORI;ch++){ float v=o[(size_t)ch*NPIX]; if(v>bv){bv=v;ai=ch;} }
        of=((float)ai*2.0f-90.0f)*0.017453292519943295f*m;
    }
    out[ORI_OFF+i]=of;
}

extern "C" void kernel_launch(void* const* d_in, const int* in_sizes, int n_in,
                              void* d_out, int out_size){
    const float* seg    =(const float*)d_in[0];
    const float* segup  =(const float*)d_in[1];
    const float* oriup  =(const float*)d_in[2];
    const float* enh    =(const float*)d_in[3];
    const float* mscore =(const float*)d_in[4];
    const float* mori   =(const float*)d_in[5];
    const float* mxo    =(const float*)d_in[6];
    const float* myo    =(const float*)d_in[7];
    float* out=(float*)d_out;

    int nSmall=(BNUM*NCELL+255)/256;
    int nBig  =(BNUM*NPIX +255)/256;
    int nVec  =(BNUM*NPIX/4+255)/256;   // 1024 blocks

    small_erode<<<nSmall,256>>>(seg);    // includes minmax init
    small_dilate<<<nSmall,256>>>();

    up1_vmin<<<nBig,256>>>(segup);       // HEAVY anchor
    up2_h4min<<<nVec,256>>>();           // light, sandwiched (2.44us measured here)
    up3_vmax<<<nBig,256>>>();            // HEAVY anchor
    up4_hmax<<<nBig,256>>>();            // HEAVY anchor (keeps clock up before detect)

    {
        dim3 g(64,BNUM);
        enh_minmax<<<g,256>>>(enh);
    }

    detect_nms<<<BNUM,1024>>>(mscore, mori, mxo, myo, out);
    finalize<<<nBig,256>>>(enh, oriup, out);
}

// round 14
// speedup vs baseline: 2.2958x; 1.0429x over previous
#include <cuda_runtime.h>
#include <cstdint>

#define BNUM 4
#define HS 64
#define WS 64
#define HU 512
#define WU 512
#define CORI 90
#define CMNT 180
#define COFF 8
#define KCAND 1024
#define NCELL (HS*WS)       // 4096
#define NPIX (HU*WU)        // 262144

// output layout (concatenated flattened returns):
// minut [4,1024,4] | keep [4,1024] | enh_vis [4,512,512] | mask_up*255 | ori_field
#define MINUT_OFF 0
#define KEEP_OFF  16384
#define ENH_OFF   20480
#define MASK_OFF  1069056
#define ORI_OFF   2117632

// -------- device scratch --------
__device__ float g_mask[BNUM*NCELL];
__device__ float g_er[BNUM*NCELL];
__device__ float g_tA[BNUM*NPIX];
__device__ float g_tB[BNUM*NPIX];
__device__ float g_maskup[BNUM*NPIX];
__device__ unsigned g_emin[BNUM];
__device__ unsigned g_emax[BNUM];

__device__ __forceinline__ unsigned f2ord(float f){
    unsigned u=__float_as_uint(f);
    return (u & 0x80000000u) ? ~u : (u | 0x80000000u);
}
__device__ __forceinline__ float ord2f(unsigned u){
    u = (u & 0x80000000u) ? (u & 0x7fffffffu) : ~u;
    return __uint_as_float(u);
}

// -------- small 5x5 opening on [B,64,64] (+ minmax init) --------
__global__ void small_erode(const float* __restrict__ seg){
    int i=blockIdx.x*blockDim.x+threadIdx.x;
    if(i<BNUM){ g_emin[i]=0xFFFFFFFFu; g_emax[i]=0u; }
    if(i>=BNUM*NCELL) return;
    int b=i/NCELL, cell=i%NCELL, r=cell/WS, c=cell%WS;
    const float* s=seg+(size_t)b*NCELL;
    int y0=r-2<0?0:r-2, y1=r+2>HS-1?HS-1:r+2;
    int x0=c-2<0?0:c-2, x1=c+2>WS-1?WS-1:c+2;
    float m=1e30f;
    for(int y=y0;y<=y1;y++)
        for(int x=x0;x<=x1;x++)
            m=fminf(m, rintf(s[y*WS+x]));
    g_er[i]=m;
}
__global__ void small_dilate(){
    int i=blockIdx.x*blockDim.x+threadIdx.x;
    if(i>=BNUM*NCELL) return;
    int b=i/NCELL, cell=i%NCELL, r=cell/WS, c=cell%WS;
    const float* s=g_er+(size_t)b*NCELL;
    int y0=r-2<0?0:r-2, y1=r+2>HS-1?HS-1:r+2;
    int x0=c-2<0?0:c-2, x1=c+2>WS-1?WS-1:c+2;
    float m=-1e30f;
    for(int y=y0;y<=y1;y++)
        for(int x=x0;x<=x1;x++)
            m=fmaxf(m, s[y*WS+x]);
    g_mask[i]=m;
}

// -------- vertical brute pools (HEAVY ANCHORS) --------
__device__ __forceinline__ float poolV(const float* s, int y, int x, bool isMin, bool doRound){
    int a0=y-19; if(a0<0)a0=0;
    int a1=y+20; if(a1>HU-1)a1=HU-1;
    float m = isMin?1e30f:-1e30f;
    for(int yy=a0;yy<=a1;yy++){
        float v=s[yy*WU+x];
        if(doRound)v=rintf(v);
        m = isMin?fminf(m,v):fmaxf(m,v);
    }
    return m;
}
__device__ __forceinline__ float poolH(const float* s, int y, int x, bool isMin){
    int a0=x-19; if(a0<0)a0=0;
    int a1=x+20; if(a1>WU-1)a1=WU-1;
    const float* row=s+(size_t)y*WU;
    float m = isMin?1e30f:-1e30f;
    for(int xx=a0;xx<=a1;xx++){
        float v=row[xx];
        m = isMin?fminf(m,v):fmaxf(m,v);
    }
    return m;
}
__global__ void up1_vmin(const float* __restrict__ segup){
    int i=blockIdx.x*blockDim.x+threadIdx.x; if(i>=BNUM*NPIX)return;
    int b=i/NPIX, p=i%NPIX;
    g_tA[i]=poolV(segup+(size_t)b*NPIX, p/WU, p%WU, true, true);
}
__global__ void up4_hmax(){
    int i=blockIdx.x*blockDim.x+threadIdx.x; if(i>=BNUM*NPIX)return;
    int b=i/NPIX, p=i%NPIX;
    g_maskup[i]=poolH(g_tA+(size_t)b*NPIX, p/WU, p%WU, false);
}

// -------- hmin as float4 quad pool (light, sandwiched; proven in this slot) --------
__global__ void __launch_bounds__(256) up2_h4min(){
    int i=blockIdx.x*256+threadIdx.x;
    if(i>=BNUM*NPIX/4) return;
    int b=i/(NPIX/4); int rem=i%(NPIX/4);
    int row=rem/(WU/4); int x0=(rem%(WU/4))*4;
    const float* rp = g_tA + (size_t)b*NPIX + (size_t)row*WU;
    const float NEU=1e30f;
    float qm[11];
    float e1,e2,e3,f0,f1,f2;
    #pragma unroll
    for(int q=0;q<11;q++){
        int bs=x0-20+4*q;
        float a0,a1,a2,a3;
        if(bs>=0 && bs+3<WU){
            float4 v=*reinterpret_cast<const float4*>(rp+bs);
            a0=v.x; a1=v.y; a2=v.z; a3=v.w;
        } else {
            a0=(bs  >=0 && bs  <WU)? rp[bs  ] : NEU;
            a1=(bs+1>=0 && bs+1<WU)? rp[bs+1] : NEU;
            a2=(bs+2>=0 && bs+2<WU)? rp[bs+2] : NEU;
            a3=(bs+3>=0 && bs+3<WU)? rp[bs+3] : NEU;
        }
        if(q==0){ e1=a1; e2=a2; e3=a3; }
        if(q==10){ f0=a0; f1=a1; f2=a2; }
        qm[q]=fminf(fminf(a0,a1),fminf(a2,a3));
    }
    float core=qm[1];
    #pragma unroll
    for(int k=2;k<=9;k++) core=fminf(core,qm[k]);
    float4 o;
    o.x=fminf(fminf(core,fminf(e1,e2)),fminf(e3,f0));
    o.y=fminf(fminf(core,fminf(e2,e3)),fminf(f0,f1));
    o.z=fminf(fminf(core,e3),fminf(f0,fminf(f1,f2)));
    o.w=fminf(core,qm[10]);
    *reinterpret_cast<float4*>(g_tB + (size_t)b*NPIX + (size_t)row*WU + x0) = o;
}

// -------- vmax as float4 vertical quad (light #2): 40 float4 loads / 4 outputs --------
__global__ void __launch_bounds__(256) up3_v4max(){
    int i=blockIdx.x*256+threadIdx.x;
    if(i>=BNUM*NPIX/4) return;
    int b=i/(NPIX/4); int rem=i%(NPIX/4);
    int y=rem/(WU/4); int x0=(rem%(WU/4))*4;
    const float* base = g_tB + (size_t)b*NPIX + x0;
    float m0=-1e30f, m1=-1e30f, m2=-1e30f, m3=-1e30f;
    int a0=y-19; if(a0<0)a0=0;
    int a1=y+20; if(a1>HU-1)a1=HU-1;
    #pragma unroll 8
    for(int yy=a0;yy<=a1;yy++){
        float4 v=*reinterpret_cast<const float4*>(base+(size_t)yy*WU);
        m0=fmaxf(m0,v.x); m1=fmaxf(m1,v.y); m2=fmaxf(m2,v.z); m3=fmaxf(m3,v.w);
    }
    float4 o; o.x=m0; o.y=m1; o.z=m2; o.w=m3;
    *reinterpret_cast<float4*>(g_tA + (size_t)b*NPIX + (size_t)y*WU + x0) = o;
}

// -------- enhanced min/max per batch --------
__global__ void enh_minmax(const float* __restrict__ enh){
    int b=blockIdx.y;
    const float* e=enh+(size_t)b*NPIX;
    const float* m=g_maskup+(size_t)b*NPIX;
    float mn=1e30f, mx=-1e30f;
    for(int p=blockIdx.x*blockDim.x+threadIdx.x; p<NPIX; p+=gridDim.x*blockDim.x){
        float v=e[p]*m[p];
        mn=fminf(mn,v); mx=fmaxf(mx,v);
    }
    for(int o=16;o;o>>=1){
        mn=fminf(mn,__shfl_down_sync(0xFFFFFFFFu,mn,o));
        mx=fmaxf(mx,__shfl_down_sync(0xFFFFFFFFu,mx,o));
    }
    __shared__ float smn[8], smx[8];
    int lane=threadIdx.x&31, w=threadIdx.x>>5;
    if(lane==0){ smn[w]=mn; smx[w]=mx; }
    __syncthreads();
    if(threadIdx.x==0){
        int nw=blockDim.x>>5;
        for(int i=1;i<nw;i++){ mn=fminf(mn,smn[i]); mx=fmaxf(mx,smx[i]); }
        atomicMin(&g_emin[b], f2ord(mn));
        atomicMax(&g_emax[b], f2ord(mx));
    }
}

// -------- detect (top-k + NMS), one block per batch --------
__global__ void __launch_bounds__(1024) detect_nms(
    const float* __restrict__ mscore, const float* __restrict__ mori,
    const float* __restrict__ mxo,    const float* __restrict__ myo,
    float* __restrict__ out)
{
    int b=blockIdx.x, tid=threadIdx.x;
    __shared__ unsigned long long keys[4096];   // 32KB
    __shared__ int s_nv;
    float* sx=(float*)(keys+1024);
    float* sy=(float*)(keys+1536);
    float* sa=(float*)(keys+2048);
    unsigned char* skeep=(unsigned char*)(keys+2560);

    const float* sc=mscore+(size_t)b*NCELL;
    const float* mk=g_mask +(size_t)b*NCELL;

    bool anyv=false;
    for(int t=tid;t<NCELL;t+=1024){
        float v=sc[t]*mk[t];
        bool val = v>0.5f;
        anyv |= val;
        float mv = val ? v : -1.0f;
        keys[t] = ((unsigned long long)(~f2ord(mv))<<32) | (unsigned)t;
    }
    if(__syncthreads_count(anyv)==0){
        float* om=out + MINUT_OFF + (size_t)b*KCAND*4 + (size_t)tid*4;
        om[0]=0.0f; om[1]=0.0f; om[2]=0.0f; om[3]=0.0f;
        out[KEEP_OFF + (size_t)b*KCAND + tid]=0.0f;
        return;
    }

    for(int k=2;k<=4096;k<<=1){
        for(int j=k>>1;j>0;j>>=1){
            for(int i=tid;i<4096;i+=1024){
                int ixj=i^j;
                if(ixj>i){
                    unsigned long long a=keys[i], c=keys[ixj];
                    bool up=((i&k)==0);
                    if((a>c)==up){ keys[i]=c; keys[ixj]=a; }
                }
            }
            __syncthreads();
        }
    }

    unsigned long long key=keys[tid];
    int idx=(int)(key & 0xFFFFFFFFull);
    float score=sc[idx]*mk[idx];
    bool valid = score>0.5f;
    float xc=0.0f, yc=0.0f, ang=0.0f;
    if(!valid) score=0.0f;
    if(valid){
        int r=idx>>6, c=idx&63;
        const float* o=mori+(size_t)b*CMNT*NCELL+idx;
        int ai=0; float bv=o[0];
        for(int ch=1;ch<CMNT;ch++){ float v=o[(size_t)ch*NCELL]; if(v>bv){bv=v;ai=ch;} }
        const float* xo=mxo+(size_t)b*COFF*NCELL+idx;
        int xi=0; float bx=xo[0];
        for(int ch=1;ch<COFF;ch++){ float v=xo[(size_t)ch*NCELL]; if(v>bx){bx=v;xi=ch;} }
        const float* yo=myo+(size_t)b*COFF*NCELL+idx;
        int yi=0; float by=yo[0];
        for(int ch=1;ch<COFF;ch++){ float v=yo[(size_t)ch*NCELL]; if(v>by){by=v;yi=ch;} }
        ang=((float)ai*2.0f-89.0f)*0.017453292519943295f;
        xc=(float)c*8.0f+(float)xi;
        yc=(float)r*8.0f+(float)yi;
    }
    if(tid==0) s_nv=0;
    __syncthreads();
    sx[tid]=xc; sy[tid]=yc; sa[tid]=ang; skeep[tid]=valid?1:0;
    atomicMax(&s_nv, valid?(tid+1):0);
    __syncthreads();
    int nv=s_nv;
    for(int i=0;i<nv;i++){
        if(skeep[i] && tid>i && skeep[tid]){
            float dx=sx[tid]-sx[i], dy=sy[tid]-sy[i];
            float d=sqrtf(dx*dx+dy*dy);
            float da=fabsf(sa[tid]-sa[i]);
            da=fminf(da, 6.2831853071795864f-da);
            if(d<16.0f && da<0.52359877559829887f) skeep[tid]=0;
        }
        __syncthreads();
    }
    float kf = skeep[tid]?1.0f:0.0f;
    float* om=out + MINUT_OFF + (size_t)b*KCAND*4 + (size_t)tid*4;
    om[0]=kf*xc; om[1]=kf*yc; om[2]=kf*ang; om[3]=kf*score;
    out[KEEP_OFF + (size_t)b*KCAND + tid]=kf;
}

// -------- finalize: enh_vis, mask*255, ori_field (mask-predicated argmax) --------
__global__ void finalize(const float* __restrict__ enh, const float* __restrict__ oriup,
                         float* __restrict__ out){
    int i=blockIdx.x*blockDim.x+threadIdx.x;
    if(i>=BNUM*NPIX) return;
    int b=i/NPIX, p=i%NPIX;
    float m=g_maskup[i];
    out[MASK_OFF+i]=m*255.0f;
    float emin=ord2f(g_emin[b]);
    float emax=ord2f(g_emax[b]);
    float e=enh[i]*m;
    out[ENH_OFF+i]=(e-emin)/(emax-emin+1e-8f)*255.0f;
    float of=0.0f;
    if(m!=0.0f){
        const float* o=oriup+(size_t)b*CORI*NPIX+p;
        int ai=0; float bv=o[0];
        for(int ch=1;ch<CORI;ch++){ float v=o[(size_t)ch*NPIX]; if(v>bv){bv=v;ai=ch;} }
        of=((float)ai*2.0f-90.0f)*0.017453292519943295f*m;
    }
    out[ORI_OFF+i]=of;
}

extern "C" void kernel_launch(void* const* d_in, const int* in_sizes, int n_in,
                              void* d_out, int out_size){
    const float* seg    =(const float*)d_in[0];
    const float* segup  =(const float*)d_in[1];
    const float* oriup  =(const float*)d_in[2];
    const float* enh    =(const float*)d_in[3];
    const float* mscore =(const float*)d_in[4];
    const float* mori   =(const float*)d_in[5];
    const float* mxo    =(const float*)d_in[6];
    const float* myo    =(const float*)d_in[7];
    float* out=(float*)d_out;

    int nSmall=(BNUM*NCELL+255)/256;
    int nBig  =(BNUM*NPIX +255)/256;
    int nVec  =(BNUM*NPIX/4+255)/256;   // 1024 blocks

    small_erode<<<nSmall,256>>>(seg);    // includes minmax init
    small_dilate<<<nSmall,256>>>();

    up1_vmin<<<nBig,256>>>(segup);       // HEAVY anchor
    up2_h4min<<<nVec,256>>>();           // light (proven in this slot)
    up3_v4max<<<nVec,256>>>();           // light (new this round)
    up4_hmax<<<nBig,256>>>();            // HEAVY anchor before detect

    {
        dim3 g(64,BNUM);
        enh_minmax<<<g,256>>>(enh);
    }

    detect_nms<<<BNUM,1024>>>(mscore, mori, mxo, myo, out);
    finalize<<<nBig,256>>>(enh, oriup, out);
}

// round 15
// speedup vs baseline: 2.2972x; 1.0006x over previous
#include <cuda_runtime.h>
#include <cstdint>

#define BNUM 4
#define HS 64
#define WS 64
#define HU 512
#define WU 512
#define CORI 90
#define CMNT 180
#define COFF 8
#define KCAND 1024
#define NCELL (HS*WS)       // 4096
#define NPIX (HU*WU)        // 262144

// output layout (concatenated flattened returns):
// minut [4,1024,4] | keep [4,1024] | enh_vis [4,512,512] | mask_up*255 | ori_field
#define MINUT_OFF 0
#define KEEP_OFF  16384
#define ENH_OFF   20480
#define MASK_OFF  1069056
#define ORI_OFF   2117632

// -------- device scratch --------
__device__ float g_mask[BNUM*NCELL];
__device__ float g_er[BNUM*NCELL];
__device__ float g_tA[BNUM*NPIX];
__device__ float g_tB[BNUM*NPIX];
__device__ float g_maskup[BNUM*NPIX];
__device__ unsigned g_emin[BNUM];
__device__ unsigned g_emax[BNUM];

__device__ __forceinline__ unsigned f2ord(float f){
    unsigned u=__float_as_uint(f);
    return (u & 0x80000000u) ? ~u : (u | 0x80000000u);
}
__device__ __forceinline__ float ord2f(unsigned u){
    u = (u & 0x80000000u) ? (u & 0x7fffffffu) : ~u;
    return __uint_as_float(u);
}

// -------- small 5x5 opening on [B,64,64] (+ minmax init) --------
__global__ void small_erode(const float* __restrict__ seg){
    int i=blockIdx.x*blockDim.x+threadIdx.x;
    if(i<BNUM){ g_emin[i]=0xFFFFFFFFu; g_emax[i]=0u; }
    if(i>=BNUM*NCELL) return;
    int b=i/NCELL, cell=i%NCELL, r=cell/WS, c=cell%WS;
    const float* s=seg+(size_t)b*NCELL;
    int y0=r-2<0?0:r-2, y1=r+2>HS-1?HS-1:r+2;
    int x0=c-2<0?0:c-2, x1=c+2>WS-1?WS-1:c+2;
    float m=1e30f;
    for(int y=y0;y<=y1;y++)
        for(int x=x0;x<=x1;x++)
            m=fminf(m, rintf(s[y*WS+x]));
    g_er[i]=m;
}
__global__ void small_dilate(){
    int i=blockIdx.x*blockDim.x+threadIdx.x;
    if(i>=BNUM*NCELL) return;
    int b=i/NCELL, cell=i%NCELL, r=cell/WS, c=cell%WS;
    const float* s=g_er+(size_t)b*NCELL;
    int y0=r-2<0?0:r-2, y1=r+2>HS-1?HS-1:r+2;
    int x0=c-2<0?0:c-2, x1=c+2>WS-1?WS-1:c+2;
    float m=-1e30f;
    for(int y=y0;y<=y1;y++)
        for(int x=x0;x<=x1;x++)
            m=fmaxf(m, s[y*WS+x]);
    g_mask[i]=m;
}

// -------- horizontal brute pool helper (up4 HEAVY anchor) --------
__device__ __forceinline__ float poolH(const float* s, int y, int x, bool isMin){
    int a0=x-19; if(a0<0)a0=0;
    int a1=x+20; if(a1>WU-1)a1=WU-1;
    const float* row=s+(size_t)y*WU;
    float m = isMin?1e30f:-1e30f;
    for(int xx=a0;xx<=a1;xx++){
        float v=row[xx];
        m = isMin?fminf(m,v):fmaxf(m,v);
    }
    return m;
}
__global__ void up4_hmax(){
    int i=blockIdx.x*blockDim.x+threadIdx.x; if(i>=BNUM*NPIX)return;
    int b=i/NPIX, p=i%NPIX;
    g_maskup[i]=poolH(g_tA+(size_t)b*NPIX, p/WU, p%WU, false);
}

// -------- vmin as float4 vertical quad + rint (light, chain head) --------
__global__ void __launch_bounds__(256) up1_v4min(const float* __restrict__ segup){
    int i=blockIdx.x*256+threadIdx.x;
    if(i>=BNUM*NPIX/4) return;
    int b=i/(NPIX/4); int rem=i%(NPIX/4);
    int y=rem/(WU/4); int x0=(rem%(WU/4))*4;
    const float* base = segup + (size_t)b*NPIX + x0;
    float m0=1e30f, m1=1e30f, m2=1e30f, m3=1e30f;
    int a0=y-19; if(a0<0)a0=0;
    int a1=y+20; if(a1>HU-1)a1=HU-1;
    #pragma unroll 8
    for(int yy=a0;yy<=a1;yy++){
        float4 v=*reinterpret_cast<const float4*>(base+(size_t)yy*WU);
        m0=fminf(m0,rintf(v.x)); m1=fminf(m1,rintf(v.y));
        m2=fminf(m2,rintf(v.z)); m3=fminf(m3,rintf(v.w));
    }
    float4 o; o.x=m0; o.y=m1; o.z=m2; o.w=m3;
    *reinterpret_cast<float4*>(g_tA + (size_t)b*NPIX + (size_t)y*WU + x0) = o;
}

// -------- hmin as float4 quad pool (light, proven in this slot) --------
__global__ void __launch_bounds__(256) up2_h4min(){
    int i=blockIdx.x*256+threadIdx.x;
    if(i>=BNUM*NPIX/4) return;
    int b=i/(NPIX/4); int rem=i%(NPIX/4);
    int row=rem/(WU/4); int x0=(rem%(WU/4))*4;
    const float* rp = g_tA + (size_t)b*NPIX + (size_t)row*WU;
    const float NEU=1e30f;
    float qm[11];
    float e1,e2,e3,f0,f1,f2;
    #pragma unroll
    for(int q=0;q<11;q++){
        int bs=x0-20+4*q;
        float a0,a1,a2,a3;
        if(bs>=0 && bs+3<WU){
            float4 v=*reinterpret_cast<const float4*>(rp+bs);
            a0=v.x; a1=v.y; a2=v.z; a3=v.w;
        } else {
            a0=(bs  >=0 && bs  <WU)? rp[bs  ] : NEU;
            a1=(bs+1>=0 && bs+1<WU)? rp[bs+1] : NEU;
            a2=(bs+2>=0 && bs+2<WU)? rp[bs+2] : NEU;
            a3=(bs+3>=0 && bs+3<WU)? rp[bs+3] : NEU;
        }
        if(q==0){ e1=a1; e2=a2; e3=a3; }
        if(q==10){ f0=a0; f1=a1; f2=a2; }
        qm[q]=fminf(fminf(a0,a1),fminf(a2,a3));
    }
    float core=qm[1];
    #pragma unroll
    for(int k=2;k<=9;k++) core=fminf(core,qm[k]);
    float4 o;
    o.x=fminf(fminf(core,fminf(e1,e2)),fminf(e3,f0));
    o.y=fminf(fminf(core,fminf(e2,e3)),fminf(f0,f1));
    o.z=fminf(fminf(core,e3),fminf(f0,fminf(f1,f2)));
    o.w=fminf(core,qm[10]);
    *reinterpret_cast<float4*>(g_tB + (size_t)b*NPIX + (size_t)row*WU + x0) = o;
}

// -------- vmax as float4 vertical quad (light, proven in this slot) --------
__global__ void __launch_bounds__(256) up3_v4max(){
    int i=blockIdx.x*256+threadIdx.x;
    if(i>=BNUM*NPIX/4) return;
    int b=i/(NPIX/4); int rem=i%(NPIX/4);
    int y=rem/(WU/4); int x0=(rem%(WU/4))*4;
    const float* base = g_tB + (size_t)b*NPIX + x0;
    float m0=-1e30f, m1=-1e30f, m2=-1e30f, m3=-1e30f;
    int a0=y-19; if(a0<0)a0=0;
    int a1=y+20; if(a1>HU-1)a1=HU-1;
    #pragma unroll 8
    for(int yy=a0;yy<=a1;yy++){
        float4 v=*reinterpret_cast<const float4*>(base+(size_t)yy*WU);
        m0=fmaxf(m0,v.x); m1=fmaxf(m1,v.y); m2=fmaxf(m2,v.z); m3=fmaxf(m3,v.w);
    }
    float4 o; o.x=m0; o.y=m1; o.z=m2; o.w=m3;
    *reinterpret_cast<float4*>(g_tA + (size_t)b*NPIX + (size_t)y*WU + x0) = o;
}

// -------- enhanced min/max per batch --------
__global__ void enh_minmax(const float* __restrict__ enh){
    int b=blockIdx.y;
    const float* e=enh+(size_t)b*NPIX;
    const float* m=g_maskup+(size_t)b*NPIX;
    float mn=1e30f, mx=-1e30f;
    for(int p=blockIdx.x*blockDim.x+threadIdx.x; p<NPIX; p+=gridDim.x*blockDim.x){
        float v=e[p]*m[p];
        mn=fminf(mn,v); mx=fmaxf(mx,v);
    }
    for(int o=16;o;o>>=1){
        mn=fminf(mn,__shfl_down_sync(0xFFFFFFFFu,mn,o));
        mx=fmaxf(mx,__shfl_down_sync(0xFFFFFFFFu,mx,o));
    }
    __shared__ float smn[8], smx[8];
    int lane=threadIdx.x&31, w=threadIdx.x>>5;
    if(lane==0){ smn[w]=mn; smx[w]=mx; }
    __syncthreads();
    if(threadIdx.x==0){
        int nw=blockDim.x>>5;
        for(int i=1;i<nw;i++){ mn=fminf(mn,smn[i]); mx=fmaxf(mx,smx[i]); }
        atomicMin(&g_emin[b], f2ord(mn));
        atomicMax(&g_emax[b], f2ord(mx));
    }
}

// -------- detect (top-k + NMS), one block per batch --------
__global__ void __launch_bounds__(1024) detect_nms(
    const float* __restrict__ mscore, const float* __restrict__ mori,
    const float* __restrict__ mxo,    const float* __restrict__ myo,
    float* __restrict__ out)
{
    int b=blockIdx.x, tid=threadIdx.x;
    __shared__ unsigned long long keys[4096];   // 32KB
    __shared__ int s_nv;
    float* sx=(float*)(keys+1024);
    float* sy=(float*)(keys+1536);
    float* sa=(float*)(keys+2048);
    unsigned char* skeep=(unsigned char*)(keys+2560);

    const float* sc=mscore+(size_t)b*NCELL;
    const float* mk=g_mask +(size_t)b*NCELL;

    bool anyv=false;
    for(int t=tid;t<NCELL;t+=1024){
        float v=sc[t]*mk[t];
        bool val = v>0.5f;
        anyv |= val;
        float mv = val ? v : -1.0f;
        keys[t] = ((unsigned long long)(~f2ord(mv))<<32) | (unsigned)t;
    }
    if(__syncthreads_count(anyv)==0){
        float* om=out + MINUT_OFF + (size_t)b*KCAND*4 + (size_t)tid*4;
        om[0]=0.0f; om[1]=0.0f; om[2]=0.0f; om[3]=0.0f;
        out[KEEP_OFF + (size_t)b*KCAND + tid]=0.0f;
        return;
    }

    for(int k=2;k<=4096;k<<=1){
        for(int j=k>>1;j>0;j>>=1){
            for(int i=tid;i<4096;i+=1024){
                int ixj=i^j;
                if(ixj>i){
                    unsigned long long a=keys[i], c=keys[ixj];
                    bool up=((i&k)==0);
                    if((a>c)==up){ keys[i]=c; keys[ixj]=a; }
                }
            }
            __syncthreads();
        }
    }

    unsigned long long key=keys[tid];
    int idx=(int)(key & 0xFFFFFFFFull);
    float score=sc[idx]*mk[idx];
    bool valid = score>0.5f;
    float xc=0.0f, yc=0.0f, ang=0.0f;
    if(!valid) score=0.0f;
    if(valid){
        int r=idx>>6, c=idx&63;
        const float* o=mori+(size_t)b*CMNT*NCELL+idx;
        int ai=0; float bv=o[0];
        for(int ch=1;ch<CMNT;ch++){ float v=o[(size_t)ch*NCELL]; if(v>bv){bv=v;ai=ch;} }
        const float* xo=mxo+(size_t)b*COFF*NCELL+idx;
        int xi=0; float bx=xo[0];
        for(int ch=1;ch<COFF;ch++){ float v=xo[(size_t)ch*NCELL]; if(v>bx){bx=v;xi=ch;} }
        const float* yo=myo+(size_t)b*COFF*NCELL+idx;
        int yi=0; float by=yo[0];
        for(int ch=1;ch<COFF;ch++){ float v=yo[(size_t)ch*NCELL]; if(v>by){by=v;yi=ch;} }
        ang=((float)ai*2.0f-89.0f)*0.017453292519943295f;
        xc=(float)c*8.0f+(float)xi;
        yc=(float)r*8.0f+(float)yi;
    }
    if(tid==0) s_nv=0;
    __syncthreads();
    sx[tid]=xc; sy[tid]=yc; sa[tid]=ang; skeep[tid]=valid?1:0;
    atomicMax(&s_nv, valid?(tid+1):0);
    __syncthreads();
    int nv=s_nv;
    for(int i=0;i<nv;i++){
        if(skeep[i] && tid>i && skeep[tid]){
            float dx=sx[tid]-sx[i], dy=sy[tid]-sy[i];
            float d=sqrtf(dx*dx+dy*dy);
            float da=fabsf(sa[tid]-sa[i]);
            da=fminf(da, 6.2831853071795864f-da);
            if(d<16.0f && da<0.52359877559829887f) skeep[tid]=0;
        }
        __syncthreads();
    }
    float kf = skeep[tid]?1.0f:0.0f;
    float* om=out + MINUT_OFF + (size_t)b*KCAND*4 + (size_t)tid*4;
    om[0]=kf*xc; om[1]=kf*yc; om[2]=kf*ang; om[3]=kf*score;
    out[KEEP_OFF + (size_t)b*KCAND + tid]=kf;
}

// -------- finalize: enh_vis, mask*255, ori_field (mask-predicated argmax) --------
__global__ void finalize(const float* __restrict__ enh, const float* __restrict__ oriup,
                         float* __restrict__ out){
    int i=blockIdx.x*blockDim.x+threadIdx.x;
    if(i>=BNUM*NPIX) return;
    int b=i/NPIX, p=i%NPIX;
    float m=g_maskup[i];
    out[MASK_OFF+i]=m*255.0f;
    float emin=ord2f(g_emin[b]);
    float emax=ord2f(g_emax[b]);
    float e=enh[i]*m;
    out[ENH_OFF+i]=(e-emin)/(emax-emin+1e-8f)*255.0f;
    float of=0.0f;
    if(m!=0.0f){
        const float* o=oriup+(size_t)b*CORI*NPIX+p;
        int ai=0; float bv=o[0];
        for(int ch=1;ch<CORI;ch++){ float v=o[(size_t)ch*NPIX]; if(v>bv){bv=v;ai=ch;} }
        of=((float)ai*2.0f-90.0f)*0.017453292519943295f*m;
    }
    out[ORI_OFF+i]=of;
}

extern "C" void kernel_launch(void* const* d_in, const int* in_sizes, int n_in,
                              void* d_out, int out_size){
    const float* seg    =(const float*)d_in[0];
    const float* segup  =(const float*)d_in[1];
    const float* oriup  =(const float*)d_in[2];
    const float* enh    =(const float*)d_in[3];
    const float* mscore =(const float*)d_in[4];
    const float* mori   =(const float*)d_in[5];
    const float* mxo    =(const float*)d_in[6];
    const float* myo    =(const float*)d_in[7];
    float* out=(float*)d_out;

    int nSmall=(BNUM*NCELL+255)/256;
    int nBig  =(BNUM*NPIX +255)/256;
    int nVec  =(BNUM*NPIX/4+255)/256;   // 1024 blocks

    small_erode<<<nSmall,256>>>(seg);    // includes minmax init
    small_dilate<<<nSmall,256>>>();

    up1_v4min<<<nVec,256>>>(segup);      // light (new this round)
    up2_h4min<<<nVec,256>>>();           // light (proven)
    up3_v4max<<<nVec,256>>>();           // light (proven)
    up4_hmax<<<nBig,256>>>();            // HEAVY anchor before detect

    {
        dim3 g(64,BNUM);
        enh_minmax<<<g,256>>>(enh);
    }

    detect_nms<<<BNUM,1024>>>(mscore, mori, mxo, myo, out);
    finalize<<<nBig,256>>>(enh, oriup, out);
}

// round 16
// speedup vs baseline: 2.3882x; 1.0396x over previous
#include <cuda_runtime.h>
#include <cstdint>

#define BNUM 4
#define HS 64
#define WS 64
#define HU 512
#define WU 512
#define CORI 90
#define CMNT 180
#define COFF 8
#define KCAND 1024
#define NCELL (HS*WS)       // 4096
#define NPIX (HU*WU)        // 262144

// output layout (concatenated flattened returns):
// minut [4,1024,4] | keep [4,1024] | enh_vis [4,512,512] | mask_up*255 | ori_field
#define MINUT_OFF 0
#define KEEP_OFF  16384
#define ENH_OFF   20480
#define MASK_OFF  1069056
#define ORI_OFF   2117632

// -------- device scratch --------
__device__ float g_mask[BNUM*NCELL];
__device__ float g_er[BNUM*NCELL];
__device__ float g_tA[BNUM*NPIX];
__device__ float g_tB[BNUM*NPIX];
__device__ float g_maskup[BNUM*NPIX];
__device__ unsigned g_emin[BNUM];
__device__ unsigned g_emax[BNUM];

__device__ __forceinline__ unsigned f2ord(float f){
    unsigned u=__float_as_uint(f);
    return (u & 0x80000000u) ? ~u : (u | 0x80000000u);
}
__device__ __forceinline__ float ord2f(unsigned u){
    u = (u & 0x80000000u) ? (u & 0x7fffffffu) : ~u;
    return __uint_as_float(u);
}

// -------- small 5x5 opening on [B,64,64] (+ minmax init) --------
__global__ void small_erode(const float* __restrict__ seg){
    int i=blockIdx.x*blockDim.x+threadIdx.x;
    if(i<BNUM){ g_emin[i]=0xFFFFFFFFu; g_emax[i]=0u; }
    if(i>=BNUM*NCELL) return;
    int b=i/NCELL, cell=i%NCELL, r=cell/WS, c=cell%WS;
    const float* s=seg+(size_t)b*NCELL;
    int y0=r-2<0?0:r-2, y1=r+2>HS-1?HS-1:r+2;
    int x0=c-2<0?0:c-2, x1=c+2>WS-1?WS-1:c+2;
    float m=1e30f;
    for(int y=y0;y<=y1;y++)
        for(int x=x0;x<=x1;x++)
            m=fminf(m, rintf(s[y*WS+x]));
    g_er[i]=m;
}
__global__ void small_dilate(){
    int i=blockIdx.x*blockDim.x+threadIdx.x;
    if(i>=BNUM*NCELL) return;
    int b=i/NCELL, cell=i%NCELL, r=cell/WS, c=cell%WS;
    const float* s=g_er+(size_t)b*NCELL;
    int y0=r-2<0?0:r-2, y1=r+2>HS-1?HS-1:r+2;
    int x0=c-2<0?0:c-2, x1=c+2>WS-1?WS-1:c+2;
    float m=-1e30f;
    for(int y=y0;y<=y1;y++)
        for(int x=x0;x<=x1;x++)
            m=fmaxf(m, s[y*WS+x]);
    g_mask[i]=m;
}

// -------- horizontal brute pool helper (up4 HEAVY anchor) --------
__device__ __forceinline__ float poolH(const float* s, int y, int x, bool isMin){
    int a0=x-19; if(a0<0)a0=0;
    int a1=x+20; if(a1>WU-1)a1=WU-1;
    const float* row=s+(size_t)y*WU;
    float m = isMin?1e30f:-1e30f;
    for(int xx=a0;xx<=a1;xx++){
        float v=row[xx];
        m = isMin?fminf(m,v):fmaxf(m,v);
    }
    return m;
}
__global__ void up4_hmax(){
    int i=blockIdx.x*blockDim.x+threadIdx.x; if(i>=BNUM*NPIX)return;
    int b=i/NPIX, p=i%NPIX;
    g_maskup[i]=poolH(g_tA+(size_t)b*NPIX, p/WU, p%WU, false);
}

// -------- vmin as float4 vertical quad + rint (light, chain head) --------
__global__ void __launch_bounds__(256) up1_v4min(const float* __restrict__ segup){
    int i=blockIdx.x*256+threadIdx.x;
    if(i>=BNUM*NPIX/4) return;
    int b=i/(NPIX/4); int rem=i%(NPIX/4);
    int y=rem/(WU/4); int x0=(rem%(WU/4))*4;
    const float* base = segup + (size_t)b*NPIX + x0;
    float m0=1e30f, m1=1e30f, m2=1e30f, m3=1e30f;
    int a0=y-19; if(a0<0)a0=0;
    int a1=y+20; if(a1>HU-1)a1=HU-1;
    #pragma unroll 8
    for(int yy=a0;yy<=a1;yy++){
        float4 v=*reinterpret_cast<const float4*>(base+(size_t)yy*WU);
        m0=fminf(m0,rintf(v.x)); m1=fminf(m1,rintf(v.y));
        m2=fminf(m2,rintf(v.z)); m3=fminf(m3,rintf(v.w));
    }
    float4 o; o.x=m0; o.y=m1; o.z=m2; o.w=m3;
    *reinterpret_cast<float4*>(g_tA + (size_t)b*NPIX + (size_t)y*WU + x0) = o;
}

// -------- hmin as float4 quad pool (light, proven in this slot) --------
__global__ void __launch_bounds__(256) up2_h4min(){
    int i=blockIdx.x*256+threadIdx.x;
    if(i>=BNUM*NPIX/4) return;
    int b=i/(NPIX/4); int rem=i%(NPIX/4);
    int row=rem/(WU/4); int x0=(rem%(WU/4))*4;
    const float* rp = g_tA + (size_t)b*NPIX + (size_t)row*WU;
    const float NEU=1e30f;
    float qm[11];
    float e1,e2,e3,f0,f1,f2;
    #pragma unroll
    for(int q=0;q<11;q++){
        int bs=x0-20+4*q;
        float a0,a1,a2,a3;
        if(bs>=0 && bs+3<WU){
            float4 v=*reinterpret_cast<const float4*>(rp+bs);
            a0=v.x; a1=v.y; a2=v.z; a3=v.w;
        } else {
            a0=(bs  >=0 && bs  <WU)? rp[bs  ] : NEU;
            a1=(bs+1>=0 && bs+1<WU)? rp[bs+1] : NEU;
            a2=(bs+2>=0 && bs+2<WU)? rp[bs+2] : NEU;
            a3=(bs+3>=0 && bs+3<WU)? rp[bs+3] : NEU;
        }
        if(q==0){ e1=a1; e2=a2; e3=a3; }
        if(q==10){ f0=a0; f1=a1; f2=a2; }
        qm[q]=fminf(fminf(a0,a1),fminf(a2,a3));
    }
    float core=qm[1];
    #pragma unroll
    for(int k=2;k<=9;k++) core=fminf(core,qm[k]);
    float4 o;
    o.x=fminf(fminf(core,fminf(e1,e2)),fminf(e3,f0));
    o.y=fminf(fminf(core,fminf(e2,e3)),fminf(f0,f1));
    o.z=fminf(fminf(core,e3),fminf(f0,fminf(f1,f2)));
    o.w=fminf(core,qm[10]);
    *reinterpret_cast<float4*>(g_tB + (size_t)b*NPIX + (size_t)row*WU + x0) = o;
}

// -------- vmax as float4 vertical quad (light, proven in this slot) --------
__global__ void __launch_bounds__(256) up3_v4max(){
    int i=blockIdx.x*256+threadIdx.x;
    if(i>=BNUM*NPIX/4) return;
    int b=i/(NPIX/4); int rem=i%(NPIX/4);
    int y=rem/(WU/4); int x0=(rem%(WU/4))*4;
    const float* base = g_tB + (size_t)b*NPIX + x0;
    float m0=-1e30f, m1=-1e30f, m2=-1e30f, m3=-1e30f;
    int a0=y-19; if(a0<0)a0=0;
    int a1=y+20; if(a1>HU-1)a1=HU-1;
    #pragma unroll 8
    for(int yy=a0;yy<=a1;yy++){
        float4 v=*reinterpret_cast<const float4*>(base+(size_t)yy*WU);
        m0=fmaxf(m0,v.x); m1=fmaxf(m1,v.y); m2=fmaxf(m2,v.z); m3=fmaxf(m3,v.w);
    }
    float4 o; o.x=m0; o.y=m1; o.z=m2; o.w=m3;
    *reinterpret_cast<float4*>(g_tA + (size_t)b*NPIX + (size_t)y*WU + x0) = o;
}

// -------- enhanced min/max per batch --------
__global__ void enh_minmax(const float* __restrict__ enh){
    int b=blockIdx.y;
    const float* e=enh+(size_t)b*NPIX;
    const float* m=g_maskup+(size_t)b*NPIX;
    float mn=1e30f, mx=-1e30f;
    for(int p=blockIdx.x*blockDim.x+threadIdx.x; p<NPIX; p+=gridDim.x*blockDim.x){
        float v=e[p]*m[p];
        mn=fminf(mn,v); mx=fmaxf(mx,v);
    }
    for(int o=16;o;o>>=1){
        mn=fminf(mn,__shfl_down_sync(0xFFFFFFFFu,mn,o));
        mx=fmaxf(mx,__shfl_down_sync(0xFFFFFFFFu,mx,o));
    }
    __shared__ float smn[8], smx[8];
    int lane=threadIdx.x&31, w=threadIdx.x>>5;
    if(lane==0){ smn[w]=mn; smx[w]=mx; }
    __syncthreads();
    if(threadIdx.x==0){
        int nw=blockDim.x>>5;
        for(int i=1;i<nw;i++){ mn=fminf(mn,smn[i]); mx=fmaxf(mx,smx[i]); }
        atomicMin(&g_emin[b], f2ord(mn));
        atomicMax(&g_emax[b], f2ord(mx));
    }
}

// -------- detect (top-k + NMS), one block per batch --------
__global__ void __launch_bounds__(1024) detect_nms(
    const float* __restrict__ mscore, const float* __restrict__ mori,
    const float* __restrict__ mxo,    const float* __restrict__ myo,
    float* __restrict__ out)
{
    int b=blockIdx.x, tid=threadIdx.x;
    __shared__ unsigned long long keys[4096];   // 32KB
    __shared__ int s_nv;
    float* sx=(float*)(keys+1024);
    float* sy=(float*)(keys+1536);
    float* sa=(float*)(keys+2048);
    unsigned char* skeep=(unsigned char*)(keys+2560);

    const float* sc=mscore+(size_t)b*NCELL;
    const float* mk=g_mask +(size_t)b*NCELL;

    bool anyv=false;
    for(int t=tid;t<NCELL;t+=1024){
        float v=sc[t]*mk[t];
        bool val = v>0.5f;
        anyv |= val;
        float mv = val ? v : -1.0f;
        keys[t] = ((unsigned long long)(~f2ord(mv))<<32) | (unsigned)t;
    }
    if(__syncthreads_count(anyv)==0){
        float* om=out + MINUT_OFF + (size_t)b*KCAND*4 + (size_t)tid*4;
        om[0]=0.0f; om[1]=0.0f; om[2]=0.0f; om[3]=0.0f;
        out[KEEP_OFF + (size_t)b*KCAND + tid]=0.0f;
        return;
    }

    for(int k=2;k<=4096;k<<=1){
        for(int j=k>>1;j>0;j>>=1){
            for(int i=tid;i<4096;i+=1024){
                int ixj=i^j;
                if(ixj>i){
                    unsigned long long a=keys[i], c=keys[ixj];
                    bool up=((i&k)==0);
                    if((a>c)==up){ keys[i]=c; keys[ixj]=a; }
                }
            }
            __syncthreads();
        }
    }

    unsigned long long key=keys[tid];
    int idx=(int)(key & 0xFFFFFFFFull);
    float score=sc[idx]*mk[idx];
    bool valid = score>0.5f;
    float xc=0.0f, yc=0.0f, ang=0.0f;
    if(!valid) score=0.0f;
    if(valid){
        int r=idx>>6, c=idx&63;
        const float* o=mori+(size_t)b*CMNT*NCELL+idx;
        int ai=0; float bv=o[0];
        for(int ch=1;ch<CMNT;ch++){ float v=o[(size_t)ch*NCELL]; if(v>bv){bv=v;ai=ch;} }
        const float* xo=mxo+(size_t)b*COFF*NCELL+idx;
        int xi=0; float bx=xo[0];
        for(int ch=1;ch<COFF;ch++){ float v=xo[(size_t)ch*NCELL]; if(v>bx){bx=v;xi=ch;} }
        const float* yo=myo+(size_t)b*COFF*NCELL+idx;
        int yi=0; float by=yo[0];
        for(int ch=1;ch<COFF;ch++){ float v=yo[(size_t)ch*NCELL]; if(v>by){by=v;yi=ch;} }
        ang=((float)ai*2.0f-89.0f)*0.017453292519943295f;
        xc=(float)c*8.0f+(float)xi;
        yc=(float)r*8.0f+(float)yi;
    }
    if(tid==0) s_nv=0;
    __syncthreads();
    sx[tid]=xc; sy[tid]=yc; sa[tid]=ang; skeep[tid]=valid?1:0;
    atomicMax(&s_nv, valid?(tid+1):0);
    __syncthreads();
    int nv=s_nv;
    for(int i=0;i<nv;i++){
        if(skeep[i] && tid>i && skeep[tid]){
            float dx=sx[tid]-sx[i], dy=sy[tid]-sy[i];
            float d=sqrtf(dx*dx+dy*dy);
            float da=fabsf(sa[tid]-sa[i]);
            da=fminf(da, 6.2831853071795864f-da);
            if(d<16.0f && da<0.52359877559829887f) skeep[tid]=0;
        }
        __syncthreads();
    }
    float kf = skeep[tid]?1.0f:0.0f;
    float* om=out + MINUT_OFF + (size_t)b*KCAND*4 + (size_t)tid*4;
    om[0]=kf*xc; om[1]=kf*yc; om[2]=kf*ang; om[3]=kf*score;
    out[KEEP_OFF + (size_t)b*KCAND + tid]=kf;
}

// -------- finalize (float4): enh_vis, mask*255, ori_field; 4 pixels/thread --------
__global__ void __launch_bounds__(256) finalize4(const float* __restrict__ enh,
                         const float* __restrict__ oriup, float* __restrict__ out){
    int i=blockIdx.x*256+threadIdx.x;
    if(i>=BNUM*NPIX/4) return;
    int b=i/(NPIX/4); int rem=i%(NPIX/4);
    size_t off=(size_t)b*NPIX + (size_t)rem*4;
    size_t p=(size_t)rem*4;
    float4 m4=*reinterpret_cast<const float4*>(g_maskup+off);
    float4 e4=*reinterpret_cast<const float4*>(enh+off);
    // mask*255
    float4 mk; mk.x=m4.x*255.0f; mk.y=m4.y*255.0f; mk.z=m4.z*255.0f; mk.w=m4.w*255.0f;
    *reinterpret_cast<float4*>(out+MASK_OFF+off)=mk;
    // enh_vis
    float emin=ord2f(g_emin[b]);
    float emax=ord2f(g_emax[b]);
    float inv=255.0f/(emax-emin+1e-8f);
    float4 ev;
    ev.x=(e4.x*m4.x-emin)*inv; ev.y=(e4.y*m4.y-emin)*inv;
    ev.z=(e4.z*m4.z-emin)*inv; ev.w=(e4.w*m4.w-emin)*inv;
    *reinterpret_cast<float4*>(out+ENH_OFF+off)=ev;
    // ori_field (mask-predicated argmax per lane element)
    float4 of; of.x=0.0f; of.y=0.0f; of.z=0.0f; of.w=0.0f;
    float* ofp=&of.x;
    const float* mp=&m4.x;
    const float* ob=oriup+(size_t)b*CORI*NPIX;
    #pragma unroll
    for(int k=0;k<4;k++){
        float m=mp[k];
        if(m!=0.0f){
            const float* o=ob+p+k;
            int ai=0; float bv=o[0];
            for(int ch=1;ch<CORI;ch++){ float v=o[(size_t)ch*NPIX]; if(v>bv){bv=v;ai=ch;} }
            ofp[k]=((float)ai*2.0f-90.0f)*0.017453292519943295f*m;
        }
    }
    *reinterpret_cast<float4*>(out+ORI_OFF+off)=of;
}

extern "C" void kernel_launch(void* const* d_in, const int* in_sizes, int n_in,
                              void* d_out, int out_size){
    const float* seg    =(const float*)d_in[0];
    const float* segup  =(const float*)d_in[1];
    const float* oriup  =(const float*)d_in[2];
    const float* enh    =(const float*)d_in[3];
    const float* mscore =(const float*)d_in[4];
    const float* mori   =(const float*)d_in[5];
    const float* mxo    =(const float*)d_in[6];
    const float* myo    =(const float*)d_in[7];
    float* out=(float*)d_out;

    int nSmall=(BNUM*NCELL+255)/256;
    int nBig  =(BNUM*NPIX +255)/256;
    int nVec  =(BNUM*NPIX/4+255)/256;   // 1024 blocks

    small_erode<<<nSmall,256>>>(seg);    // includes minmax init
    small_dilate<<<nSmall,256>>>();

    up1_v4min<<<nVec,256>>>(segup);      // light
    up2_h4min<<<nVec,256>>>();           // light (proven)
    up3_v4max<<<nVec,256>>>();           // light (proven)
    up4_hmax<<<nBig,256>>>();            // HEAVY anchor before detect

    {
        dim3 g(64,BNUM);
        enh_minmax<<<g,256>>>(enh);
    }

    detect_nms<<<BNUM,1024>>>(mscore, mori, mxo, myo, out);
    finalize4<<<nVec,256>>>(enh, oriup, out);
}